// round 2
// baseline (speedup 1.0000x reference)
#include <cuda_runtime.h>

#define NN   2048
#define MEM  1024
#define NCTA 128
#define TPB  256

// Persistent device scratch (allocation-free rule: __device__ globals).
__device__ __align__(16) float g_Gx[NN * 5 * MEM];   // 40 MB input projection
__device__ __align__(16) float g_h[MEM];             // recurrent hidden broadcast
__device__ __align__(16) float g_v[MEM];             // z*tanh(c) broadcast
__device__ __align__(16) unsigned g_fh[NCTA];        // per-CTA h publication flags
__device__ __align__(16) unsigned g_fv[NCTA];        // per-CTA v publication flags

__device__ __forceinline__ float sigf(float x) { return 1.0f / (1.0f + expf(-x)); }

__device__ __forceinline__ float warpSum(float v) {
#pragma unroll
    for (int o = 16; o > 0; o >>= 1) v += __shfl_down_sync(0xffffffffu, v, o);
    return v;
}

// Warp-0 poll: wait until all NCTA flags >= tag, then acquire-fence.
// flags written with st.release.gpu -> volatile(relaxed) observe + fence.acq_rel
// gives the acquire side of the pairing.
__device__ __forceinline__ void poll_ge(const unsigned* flags, unsigned tag) {
    const int lane = threadIdx.x & 31;
    const uint4* p = (const uint4*)flags + lane;   // 32 lanes x 4 flags = 128
    for (;;) {
        unsigned a, b, c, d;
        asm volatile("ld.volatile.global.v4.u32 {%0,%1,%2,%3}, [%4];"
                     : "=r"(a), "=r"(b), "=r"(c), "=r"(d) : "l"(p));
        bool ok = (a >= tag) & (b >= tag) & (c >= tag) & (d >= tag);
        if (__all_sync(0xffffffffu, ok)) break;
    }
    asm volatile("fence.acq_rel.gpu;" ::: "memory");
}

__device__ __forceinline__ void st_release_u32(unsigned* p, unsigned v) {
    asm volatile("st.release.gpu.global.u32 [%0], %1;" :: "l"(p), "r"(v) : "memory");
}

// ---------------------------------------------------------------------------
// Kernel 1: Gx = inputs @ Wx + bx   (2048 x 1024) @ (1024 x 5120)
// Classic 128x128x8 SGEMM, 256 threads, 8x8 per-thread tile.
// Also resets the publication flags for this graph replay.
// ---------------------------------------------------------------------------
__global__ void __launch_bounds__(256) gemm_gx_kernel(
    const float* __restrict__ A,   // inputs (2048,1024)
    const float* __restrict__ B,   // Wx (1024,5120)
    const float* __restrict__ bx)  // (5120,)
{
    if (blockIdx.x == 0 && blockIdx.y == 0 && threadIdx.x < NCTA) {
        g_fh[threadIdx.x] = 0u;
        g_fv[threadIdx.x] = 0u;
    }

    __shared__ float As[8][128];
    __shared__ float Bs[8][132];   // +4 pad keeps float4 alignment, kills conflicts

    const int tid  = threadIdx.x;
    const int tx   = tid & 15;          // 0..15 (N direction)
    const int ty   = tid >> 4;          // 0..15 (M direction)
    const int arow = tid >> 1;          // 0..127
    const int akc  = (tid & 1) << 2;    // 0 or 4
    const int bkr  = tid >> 5;          // 0..7
    const int bcol = (tid & 31) << 2;   // 0..124

    const int m0 = blockIdx.y << 7;
    const int n0 = blockIdx.x << 7;

    const float* Aptr = A + (m0 + arow) * 1024 + akc;
    const float* Bptr = B + bkr * 5120 + n0 + bcol;

    float acc[8][8];
#pragma unroll
    for (int i = 0; i < 8; ++i)
#pragma unroll
        for (int j = 0; j < 8; ++j) acc[i][j] = 0.0f;

    for (int kt = 0; kt < 1024; kt += 8) {
        const float4 av = __ldg((const float4*)(Aptr + kt));
        const float4 bv = __ldg((const float4*)(Bptr + kt * 5120));
        As[akc + 0][arow] = av.x;
        As[akc + 1][arow] = av.y;
        As[akc + 2][arow] = av.z;
        As[akc + 3][arow] = av.w;
        *(float4*)&Bs[bkr][bcol] = bv;
        __syncthreads();

#pragma unroll
        for (int k = 0; k < 8; ++k) {
            float ar[8], br[8];
            *(float4*)(ar)     = *(const float4*)&As[k][ty * 8];
            *(float4*)(ar + 4) = *(const float4*)&As[k][ty * 8 + 4];
            *(float4*)(br)     = *(const float4*)&Bs[k][tx * 8];
            *(float4*)(br + 4) = *(const float4*)&Bs[k][tx * 8 + 4];
#pragma unroll
            for (int i = 0; i < 8; ++i)
#pragma unroll
                for (int j = 0; j < 8; ++j) acc[i][j] += ar[i] * br[j];
        }
        __syncthreads();
    }

    const int crow = m0 + ty * 8;
    const int ccol = n0 + tx * 8;
    float bxv[8];
    *(float4*)(bxv)     = __ldg((const float4*)&bx[ccol]);
    *(float4*)(bxv + 4) = __ldg((const float4*)&bx[ccol + 4]);
#pragma unroll
    for (int i = 0; i < 8; ++i) {
        float4 c0 = make_float4(acc[i][0] + bxv[0], acc[i][1] + bxv[1],
                                acc[i][2] + bxv[2], acc[i][3] + bxv[3]);
        float4 c1 = make_float4(acc[i][4] + bxv[4], acc[i][5] + bxv[5],
                                acc[i][6] + bxv[6], acc[i][7] + bxv[7]);
        *(float4*)&g_Gx[(size_t)(crow + i) * 5120 + ccol]     = c0;
        *(float4*)&g_Gx[(size_t)(crow + i) * 5120 + ccol + 4] = c1;
    }
}

// ---------------------------------------------------------------------------
// Kernel 2: persistent sequential scan. 128 CTAs; CTA s owns state dims
// m = 8s..8s+7. All recurrent weights live in REGISTERS:
//   warp w owns Wh columns 4w..4w+3 (col c -> gate c>>3, dim m0+(c&7))
//   and Wum column m0+w. Thread (w,lane) holds the k-slice
//   k = 4*(i*32+lane)..+3 for i=0..7  -> 128 + 32 weight floats per thread.
// Cross-CTA sync: per-CTA step-tagged flags (data-is-arrival), no atomics.
// ---------------------------------------------------------------------------
__global__ void __launch_bounds__(TPB, 1) scan_kernel(
    const float* __restrict__ Wh,  const float* __restrict__ bh,
    const float* __restrict__ Wum, const float* __restrict__ bum,
    const float* __restrict__ pic, const float* __restrict__ pfc,
    const float* __restrict__ poc, const float* __restrict__ pzc,
    float* __restrict__ out)
{
    __shared__ float hv[MEM];      // broadcast h (phase 1) / v (phase 2)
    __shared__ float ghs[32];      // per-column dot results

    const int tid  = threadIdx.x;
    const int m0   = blockIdx.x * 8;
    const int w    = tid >> 5;
    const int lane = tid & 31;
    const int b    = blockIdx.x;

    // ---- load recurrent weights into registers (one-time per launch) ----
    float4 wr[8][4];   // Wh: [i][c]
    float4 wm[8];      // Wum: [i]
#pragma unroll
    for (int i = 0; i < 8; ++i) {
        const int kb = (i * 32 + lane) * 4;
#pragma unroll
        for (int c = 0; c < 4; ++c) {
            const int cc   = 4 * w + c;
            const int gcol = (cc >> 3) * MEM + m0 + (cc & 7);
            wr[i][c].x = __ldg(&Wh[(kb + 0) * (4 * MEM) + gcol]);
            wr[i][c].y = __ldg(&Wh[(kb + 1) * (4 * MEM) + gcol]);
            wr[i][c].z = __ldg(&Wh[(kb + 2) * (4 * MEM) + gcol]);
            wr[i][c].w = __ldg(&Wh[(kb + 3) * (4 * MEM) + gcol]);
        }
        const int mcol = m0 + w;
        wm[i].x = __ldg(&Wum[(kb + 0) * MEM + mcol]);
        wm[i].y = __ldg(&Wum[(kb + 1) * MEM + mcol]);
        wm[i].z = __ldg(&Wum[(kb + 2) * MEM + mcol]);
        wm[i].w = __ldg(&Wum[(kb + 3) * MEM + mcol]);
    }

    // per-dim constants live in registers of threads 0..7 (warp 0)
    float bh_i = 0, bh_o = 0, bh_f = 0, bh_z = 0, bum_v = 0;
    float pic_v = 0, pfc_v = 0, poc_v = 0, pzc_v = 0;
    if (tid < 8) {
        const int m = m0 + tid;
        bh_i = bh[m];           bh_o = bh[MEM + m];
        bh_f = bh[2 * MEM + m]; bh_z = bh[3 * MEM + m];
        bum_v = bum[m];
        pic_v = pic[m]; pfc_v = pfc[m]; poc_v = poc[m]; pzc_v = pzc[m];
    }
    float cp = 0.0f, iv = 0.0f, fv = 0.0f, opre = 0.0f, gxu = 0.0f;
    float hmx = -3.402823466e38f;

    float4* hv4 = (float4*)hv;
    __syncthreads();

#pragma unroll 1
    for (unsigned t = 0; t < NN; ++t) {
        // ---- phase 1: gh = h @ Wh (our 32 cols), gates i/f/z, publish v ----
        float gxi = 0, gxo = 0, gxf = 0, gxz = 0;
        if (tid < 8) {   // Gx prefetch: independent of flags, hides under poll
            const float* gx = g_Gx + (size_t)t * (5 * MEM) + m0 + tid;
            gxi = __ldg(gx);
            gxo = __ldg(gx + MEM);
            gxf = __ldg(gx + 2 * MEM);
            gxz = __ldg(gx + 3 * MEM);
            gxu = __ldg(gx + 4 * MEM);
        }

        if (t == 0) {
            hv4[tid] = make_float4(0.f, 0.f, 0.f, 0.f);
            __syncthreads();
        } else {
            if (w == 0) poll_ge(g_fh, t);      // h of step t-1 carries tag t
            __syncthreads();
            hv4[tid] = __ldcg(((const float4*)g_h) + tid);
            __syncthreads();
        }

        float a0 = 0, a1 = 0, a2 = 0, a3 = 0;
#pragma unroll
        for (int i = 0; i < 8; ++i) {
            const float4 h4 = hv4[i * 32 + lane];
            a0 += h4.x * wr[i][0].x + h4.y * wr[i][0].y + h4.z * wr[i][0].z + h4.w * wr[i][0].w;
            a1 += h4.x * wr[i][1].x + h4.y * wr[i][1].y + h4.z * wr[i][1].z + h4.w * wr[i][1].w;
            a2 += h4.x * wr[i][2].x + h4.y * wr[i][2].y + h4.z * wr[i][2].z + h4.w * wr[i][2].w;
            a3 += h4.x * wr[i][3].x + h4.y * wr[i][3].y + h4.z * wr[i][3].z + h4.w * wr[i][3].w;
        }
        a0 = warpSum(a0); a1 = warpSum(a1); a2 = warpSum(a2); a3 = warpSum(a3);
        if (lane == 0) {
            ghs[4 * w + 0] = a0; ghs[4 * w + 1] = a1;
            ghs[4 * w + 2] = a2; ghs[4 * w + 3] = a3;
        }
        __syncthreads();

        if (w == 0) {
            float vv = 0.0f;
            if (lane < 8) {
                const float ih = ghs[lane]      + bh_i;
                const float oh = ghs[8 + lane]  + bh_o;
                const float fh = ghs[16 + lane] + bh_f;
                const float zh = ghs[24 + lane] + bh_z;
                iv   = sigf(gxi + ih + pic_v * cp);
                fv   = sigf(gxf + fh + pfc_v * cp);
                const float zv = sigf(gxz + zh + pzc_v * cp);
                opre = gxo + oh;
                vv   = zv * tanhf(cp);
            }
            float4 lo, hi;
            lo.x = __shfl_sync(0xffffffffu, vv, 0);
            lo.y = __shfl_sync(0xffffffffu, vv, 1);
            lo.z = __shfl_sync(0xffffffffu, vv, 2);
            lo.w = __shfl_sync(0xffffffffu, vv, 3);
            hi.x = __shfl_sync(0xffffffffu, vv, 4);
            hi.y = __shfl_sync(0xffffffffu, vv, 5);
            hi.z = __shfl_sync(0xffffffffu, vv, 6);
            hi.w = __shfl_sync(0xffffffffu, vv, 7);
            if (lane == 0) {
                __stcg((float4*)&g_v[m0], lo);
                __stcg((float4*)&g_v[m0 + 4], hi);
                st_release_u32(&g_fv[b], t + 1);   // v of step t carries tag t+1
            }
        }

        // ---- phase 2: u = tanh(gux + v @ Wum + bum); c, o, h; publish h ----
        if (w == 0) poll_ge(g_fv, t + 1);
        __syncthreads();
        hv4[tid] = __ldcg(((const float4*)g_v) + tid);
        __syncthreads();

        float b0 = 0.0f;
#pragma unroll
        for (int i = 0; i < 8; ++i) {
            const float4 v4 = hv4[i * 32 + lane];
            b0 += v4.x * wm[i].x + v4.y * wm[i].y + v4.z * wm[i].z + v4.w * wm[i].w;
        }
        b0 = warpSum(b0);
        if (lane == 0) ghs[w] = b0;
        __syncthreads();

        if (w == 0) {
            float hh = 0.0f;
            if (lane < 8) {
                const float u = tanhf(gxu + ghs[lane] + bum_v);
                const float c = iv * u + fv * cp;
                const float o = sigf(opre + poc_v * c);
                hh  = o * tanhf(c);
                cp  = c;
                hmx = fmaxf(hmx, hh);
            }
            float4 lo, hi;
            lo.x = __shfl_sync(0xffffffffu, hh, 0);
            lo.y = __shfl_sync(0xffffffffu, hh, 1);
            lo.z = __shfl_sync(0xffffffffu, hh, 2);
            lo.w = __shfl_sync(0xffffffffu, hh, 3);
            hi.x = __shfl_sync(0xffffffffu, hh, 4);
            hi.y = __shfl_sync(0xffffffffu, hh, 5);
            hi.z = __shfl_sync(0xffffffffu, hh, 6);
            hi.w = __shfl_sync(0xffffffffu, hh, 7);
            if (lane == 0) {
                __stcg((float4*)&g_h[m0], lo);
                __stcg((float4*)&g_h[m0 + 4], hi);
                st_release_u32(&g_fh[b], t + 1);   // h of step t carries tag t+1
            }
        }
        // no trailing CTA-wide barrier needed: next round's poll orders us
        __syncthreads();
    }

    if (tid < 8) out[m0 + tid] = hmx;
}

// ---------------------------------------------------------------------------
extern "C" void kernel_launch(void* const* d_in, const int* in_sizes, int n_in,
                              void* d_out, int out_size) {
    const float* inputs = (const float*)d_in[0];
    const float* Wx     = (const float*)d_in[1];
    const float* bx     = (const float*)d_in[2];
    const float* Wh     = (const float*)d_in[3];
    const float* bh     = (const float*)d_in[4];
    const float* Wum    = (const float*)d_in[5];
    const float* bum    = (const float*)d_in[6];
    const float* pic    = (const float*)d_in[7];
    const float* pfc    = (const float*)d_in[8];
    const float* poc    = (const float*)d_in[9];
    const float* pzc    = (const float*)d_in[10];
    float* out = (float*)d_out;

    dim3 gg(5120 / 128, 2048 / 128);
    gemm_gx_kernel<<<gg, 256>>>(inputs, Wx, bx);
    scan_kernel<<<NCTA, TPB>>>(Wh, bh, Wum, bum,
                               pic, pfc, poc, pzc, out);
}

// round 3
// speedup vs baseline: 2.4905x; 2.4905x over previous
#include <cuda_runtime.h>

#define NN   2048
#define MEM  1024
#define NCTA 128
#define TPB  256

// Persistent device scratch (allocation-free rule: __device__ globals).
__device__ __align__(16) float g_Gx[NN * 5 * MEM];   // 40 MB input projection
__device__ __align__(16) float g_h[MEM];             // recurrent hidden broadcast
__device__ __align__(16) float g_v[MEM];             // z*tanh(c) broadcast
__device__ unsigned g_bar;                           // single arrival counter

__device__ __forceinline__ float sigf(float x) { return 1.0f / (1.0f + expf(-x)); }

__device__ __forceinline__ float warpSum(float v) {
#pragma unroll
    for (int o = 16; o > 0; o >>= 1) v += __shfl_down_sync(0xffffffffu, v, o);
    return v;
}

__device__ __forceinline__ unsigned ld_acquire_u32(const unsigned* p) {
    unsigned v;
    asm volatile("ld.acquire.gpu.global.u32 %0, [%1];" : "=r"(v) : "l"(p));
    return v;
}

__device__ __forceinline__ void red_release_add(unsigned* p, unsigned v) {
    asm volatile("red.release.gpu.global.add.u32 [%0], %1;" :: "l"(p), "r"(v)
                 : "memory");
}

// ---------------------------------------------------------------------------
// Kernel 1: Gx = inputs @ Wx + bx   (2048 x 1024) @ (1024 x 5120)
// Classic 128x128x8 SGEMM, 256 threads, 8x8 per-thread tile.
// Block (0,0) also resets the scan arrival counter for this graph replay.
// ---------------------------------------------------------------------------
__global__ void __launch_bounds__(256) gemm_gx_kernel(
    const float* __restrict__ A,   // inputs (2048,1024)
    const float* __restrict__ B,   // Wx (1024,5120)
    const float* __restrict__ bx)  // (5120,)
{
    if (blockIdx.x == 0 && blockIdx.y == 0 && threadIdx.x == 0) g_bar = 0u;

    __shared__ float As[8][128];
    __shared__ float Bs[8][132];   // +4 pad keeps float4 alignment, kills conflicts

    const int tid  = threadIdx.x;
    const int tx   = tid & 15;          // 0..15 (N direction)
    const int ty   = tid >> 4;          // 0..15 (M direction)
    const int arow = tid >> 1;          // 0..127
    const int akc  = (tid & 1) << 2;    // 0 or 4
    const int bkr  = tid >> 5;          // 0..7
    const int bcol = (tid & 31) << 2;   // 0..124

    const int m0 = blockIdx.y << 7;
    const int n0 = blockIdx.x << 7;

    const float* Aptr = A + (m0 + arow) * 1024 + akc;
    const float* Bptr = B + bkr * 5120 + n0 + bcol;

    float acc[8][8];
#pragma unroll
    for (int i = 0; i < 8; ++i)
#pragma unroll
        for (int j = 0; j < 8; ++j) acc[i][j] = 0.0f;

    for (int kt = 0; kt < 1024; kt += 8) {
        const float4 av = __ldg((const float4*)(Aptr + kt));
        const float4 bv = __ldg((const float4*)(Bptr + kt * 5120));
        As[akc + 0][arow] = av.x;
        As[akc + 1][arow] = av.y;
        As[akc + 2][arow] = av.z;
        As[akc + 3][arow] = av.w;
        *(float4*)&Bs[bkr][bcol] = bv;
        __syncthreads();

#pragma unroll
        for (int k = 0; k < 8; ++k) {
            float ar[8], br[8];
            *(float4*)(ar)     = *(const float4*)&As[k][ty * 8];
            *(float4*)(ar + 4) = *(const float4*)&As[k][ty * 8 + 4];
            *(float4*)(br)     = *(const float4*)&Bs[k][tx * 8];
            *(float4*)(br + 4) = *(const float4*)&Bs[k][tx * 8 + 4];
#pragma unroll
            for (int i = 0; i < 8; ++i)
#pragma unroll
                for (int j = 0; j < 8; ++j) acc[i][j] += ar[i] * br[j];
        }
        __syncthreads();
    }

    const int crow = m0 + ty * 8;
    const int ccol = n0 + tx * 8;
    float bxv[8];
    *(float4*)(bxv)     = __ldg((const float4*)&bx[ccol]);
    *(float4*)(bxv + 4) = __ldg((const float4*)&bx[ccol + 4]);
#pragma unroll
    for (int i = 0; i < 8; ++i) {
        float4 c0 = make_float4(acc[i][0] + bxv[0], acc[i][1] + bxv[1],
                                acc[i][2] + bxv[2], acc[i][3] + bxv[3]);
        float4 c1 = make_float4(acc[i][4] + bxv[4], acc[i][5] + bxv[5],
                                acc[i][6] + bxv[6], acc[i][7] + bxv[7]);
        *(float4*)&g_Gx[(size_t)(crow + i) * 5120 + ccol]     = c0;
        *(float4*)&g_Gx[(size_t)(crow + i) * 5120 + ccol + 4] = c1;
    }
}

// ---------------------------------------------------------------------------
// Kernel 2: persistent sequential scan. 128 CTAs; CTA s owns state dims
// m = 8s..8s+7. Recurrent weights live in REGISTERS:
//   warp w owns Wh columns 4w..4w+3 (col c -> gate c>>3, dim m0+(c&7))
//   and Wum column m0+w; thread (w,lane) holds k-slices 4*(i*32+lane)..+3.
// Cross-CTA sync: ONE monotonic counter. Producer lane issues
// red.release.gpu.add (orders its own st.cg data stores, no membar/L1 flush);
// thread 0 polls ld.acquire.gpu. Valid: all 128 CTAs co-resident (<=148 SMs).
// ---------------------------------------------------------------------------
__global__ void __launch_bounds__(TPB, 1) scan_kernel(
    const float* __restrict__ Wh,  const float* __restrict__ bh,
    const float* __restrict__ Wum, const float* __restrict__ bum,
    const float* __restrict__ pic, const float* __restrict__ pfc,
    const float* __restrict__ poc, const float* __restrict__ pzc,
    float* __restrict__ out)
{
    __shared__ float hv[MEM];      // broadcast h (phase 1) / v (phase 2)
    __shared__ float ghs[32];      // per-column dot results

    const int tid  = threadIdx.x;
    const int m0   = blockIdx.x * 8;
    const int w    = tid >> 5;
    const int lane = tid & 31;

    // ---- load recurrent weights into registers (one-time per launch) ----
    float4 wr[8][4];   // Wh: [i][c]
    float4 wm[8];      // Wum: [i]
#pragma unroll
    for (int i = 0; i < 8; ++i) {
        const int kb = (i * 32 + lane) * 4;
#pragma unroll
        for (int c = 0; c < 4; ++c) {
            const int cc   = 4 * w + c;
            const int gcol = (cc >> 3) * MEM + m0 + (cc & 7);
            wr[i][c].x = __ldg(&Wh[(kb + 0) * (4 * MEM) + gcol]);
            wr[i][c].y = __ldg(&Wh[(kb + 1) * (4 * MEM) + gcol]);
            wr[i][c].z = __ldg(&Wh[(kb + 2) * (4 * MEM) + gcol]);
            wr[i][c].w = __ldg(&Wh[(kb + 3) * (4 * MEM) + gcol]);
        }
        const int mcol = m0 + w;
        wm[i].x = __ldg(&Wum[(kb + 0) * MEM + mcol]);
        wm[i].y = __ldg(&Wum[(kb + 1) * MEM + mcol]);
        wm[i].z = __ldg(&Wum[(kb + 2) * MEM + mcol]);
        wm[i].w = __ldg(&Wum[(kb + 3) * MEM + mcol]);
    }

    // per-dim constants live in registers of warp 0 lanes 0..7
    float bh_i = 0, bh_o = 0, bh_f = 0, bh_z = 0, bum_v = 0;
    float pic_v = 0, pfc_v = 0, poc_v = 0, pzc_v = 0;
    if (tid < 8) {
        const int m = m0 + tid;
        bh_i = bh[m];           bh_o = bh[MEM + m];
        bh_f = bh[2 * MEM + m]; bh_z = bh[3 * MEM + m];
        bum_v = bum[m];
        pic_v = pic[m]; pfc_v = pfc[m]; poc_v = poc[m]; pzc_v = pzc[m];
    }
    float cp = 0.0f, iv = 0.0f, fv = 0.0f, opre = 0.0f, gxu = 0.0f;
    float hmx = -3.402823466e38f;

    float4* hv4 = (float4*)hv;
    unsigned tgt = 0;
    __syncthreads();

#pragma unroll 1
    for (unsigned t = 0; t < NN; ++t) {
        // ---- phase 1: gh = h @ Wh (our 32 cols), gates i/f/z, publish v ----
        float gxi = 0, gxo = 0, gxf = 0, gxz = 0;
        if (tid < 8) {   // Gx prefetch: independent of the flag, hides under poll
            const float* gx = g_Gx + (size_t)t * (5 * MEM) + m0 + tid;
            gxi = __ldg(gx);
            gxo = __ldg(gx + MEM);
            gxf = __ldg(gx + 2 * MEM);
            gxz = __ldg(gx + 3 * MEM);
            gxu = __ldg(gx + 4 * MEM);
        }

        if (t == 0) {
            hv4[tid] = make_float4(0.f, 0.f, 0.f, 0.f);
        } else {
            if (tid == 0) while (ld_acquire_u32(&g_bar) < tgt) { }
            __syncthreads();
            hv4[tid] = __ldcg(((const float4*)g_h) + tid);
        }
        __syncthreads();

        float a0 = 0, a1 = 0, a2 = 0, a3 = 0;
#pragma unroll
        for (int i = 0; i < 8; ++i) {
            const float4 h4 = hv4[i * 32 + lane];
            a0 += h4.x * wr[i][0].x + h4.y * wr[i][0].y + h4.z * wr[i][0].z + h4.w * wr[i][0].w;
            a1 += h4.x * wr[i][1].x + h4.y * wr[i][1].y + h4.z * wr[i][1].z + h4.w * wr[i][1].w;
            a2 += h4.x * wr[i][2].x + h4.y * wr[i][2].y + h4.z * wr[i][2].z + h4.w * wr[i][2].w;
            a3 += h4.x * wr[i][3].x + h4.y * wr[i][3].y + h4.z * wr[i][3].z + h4.w * wr[i][3].w;
        }
        a0 = warpSum(a0); a1 = warpSum(a1); a2 = warpSum(a2); a3 = warpSum(a3);
        if (lane == 0) {
            ghs[4 * w + 0] = a0; ghs[4 * w + 1] = a1;
            ghs[4 * w + 2] = a2; ghs[4 * w + 3] = a3;
        }
        __syncthreads();

        if (w == 0) {
            float vv = 0.0f;
            if (lane < 8) {
                const float ih = ghs[lane]      + bh_i;
                const float oh = ghs[8 + lane]  + bh_o;
                const float fh = ghs[16 + lane] + bh_f;
                const float zh = ghs[24 + lane] + bh_z;
                iv   = sigf(gxi + ih + pic_v * cp);
                fv   = sigf(gxf + fh + pfc_v * cp);
                const float zv = sigf(gxz + zh + pzc_v * cp);
                opre = gxo + oh;
                vv   = zv * tanhf(cp);
            }
            float4 lo, hi;
            lo.x = __shfl_sync(0xffffffffu, vv, 0);
            lo.y = __shfl_sync(0xffffffffu, vv, 1);
            lo.z = __shfl_sync(0xffffffffu, vv, 2);
            lo.w = __shfl_sync(0xffffffffu, vv, 3);
            hi.x = __shfl_sync(0xffffffffu, vv, 4);
            hi.y = __shfl_sync(0xffffffffu, vv, 5);
            hi.z = __shfl_sync(0xffffffffu, vv, 6);
            hi.w = __shfl_sync(0xffffffffu, vv, 7);
            if (lane == 0) {
                __stcg((float4*)&g_v[m0], lo);
                __stcg((float4*)&g_v[m0 + 4], hi);
                red_release_add(&g_bar, 1u);       // release orders the st.cg above
            }
        }
        tgt += NCTA;   // all CTAs' phase-1 arrivals

        // ---- phase 2: u = tanh(gux + v @ Wum + bum); c, o, h; publish h ----
        if (tid == 0) while (ld_acquire_u32(&g_bar) < tgt) { }
        __syncthreads();
        hv4[tid] = __ldcg(((const float4*)g_v) + tid);
        __syncthreads();

        float b0 = 0.0f;
#pragma unroll
        for (int i = 0; i < 8; ++i) {
            const float4 v4 = hv4[i * 32 + lane];
            b0 += v4.x * wm[i].x + v4.y * wm[i].y + v4.z * wm[i].z + v4.w * wm[i].w;
        }
        b0 = warpSum(b0);
        if (lane == 0) ghs[w] = b0;
        __syncthreads();

        if (w == 0) {
            float hh = 0.0f;
            if (lane < 8) {
                const float u = tanhf(gxu + ghs[lane] + bum_v);
                const float c = iv * u + fv * cp;
                const float o = sigf(opre + poc_v * c);
                hh  = o * tanhf(c);
                cp  = c;
                hmx = fmaxf(hmx, hh);
            }
            float4 lo, hi;
            lo.x = __shfl_sync(0xffffffffu, hh, 0);
            lo.y = __shfl_sync(0xffffffffu, hh, 1);
            lo.z = __shfl_sync(0xffffffffu, hh, 2);
            lo.w = __shfl_sync(0xffffffffu, hh, 3);
            hi.x = __shfl_sync(0xffffffffu, hh, 4);
            hi.y = __shfl_sync(0xffffffffu, hh, 5);
            hi.z = __shfl_sync(0xffffffffu, hh, 6);
            hi.w = __shfl_sync(0xffffffffu, hh, 7);
            if (lane == 0) {
                __stcg((float4*)&g_h[m0], lo);
                __stcg((float4*)&g_h[m0 + 4], hi);
                red_release_add(&g_bar, 1u);
            }
        }
        tgt += NCTA;   // all CTAs' phase-2 arrivals; next iter polls this
    }

    if (tid < 8) out[m0 + tid] = hmx;
}

// ---------------------------------------------------------------------------
extern "C" void kernel_launch(void* const* d_in, const int* in_sizes, int n_in,
                              void* d_out, int out_size) {
    const float* inputs = (const float*)d_in[0];
    const float* Wx     = (const float*)d_in[1];
    const float* bx     = (const float*)d_in[2];
    const float* Wh     = (const float*)d_in[3];
    const float* bh     = (const float*)d_in[4];
    const float* Wum    = (const float*)d_in[5];
    const float* bum    = (const float*)d_in[6];
    const float* pic    = (const float*)d_in[7];
    const float* pfc    = (const float*)d_in[8];
    const float* poc    = (const float*)d_in[9];
    const float* pzc    = (const float*)d_in[10];
    float* out = (float*)d_out;

    dim3 gg(5120 / 128, 2048 / 128);
    gemm_gx_kernel<<<gg, 256>>>(inputs, Wx, bx);
    scan_kernel<<<NCTA, TPB>>>(Wh, bh, Wum, bum,
                               pic, pfc, poc, pzc, out);
}